// round 10
// baseline (speedup 1.0000x reference)
#include <cuda_runtime.h>
#include <cuda_bf16.h>
#include <cstdint>

#define NNODES 50000
#define NEDGES 800000
#define NGRAPH 256
#define INC    128
#define HID    256

#define BM 128
#define BN 128
#define BK 32
#define SA 40     // A smem row stride (shorts): 4 chunks + pad
#define SB 136    // B smem row stride (shorts): 16 chunks + pad

// Double-buffered stage layout (shorts offsets within one stage)
#define STAGE_SHORTS 18944   // 37888 bytes
#define AH_OFF 0
#define AL_OFF 5120
#define BH_OFF 10240
#define BL_OFF 14592

// Weight pool offsets in chunk-pairs (1 pair = 32B = hi16+lo16 covering 8 cols)
#define W1_0_CP 0
#define W2_0_CP 4096
#define W1S_CP  12288
#define W2S_CP  36864
#define WTOT_CP 61440

static __device__ __align__(16) float g_z[(size_t)NNODES * HID];
static __device__ __align__(16) float g_h[(size_t)NNODES * HID];
static __device__ __align__(16) uint4 g_t3[(size_t)NNODES * 64];   // chunk-interleaved t
static __device__ __align__(16) uint4 g_w3[(size_t)WTOT_CP * 2];   // chunk-interleaved weights
static __device__ unsigned g_flags[2];

__device__ __forceinline__ int ld_idx(const void* p, long long i, bool is64) {
    if (is64) return (int)__ldg(&((const long long*)p)[i]);
    return __ldg(&((const int*)p)[i]);
}

__device__ __forceinline__ void cvt_hilo(float x0, float x1, unsigned& hi, unsigned& lo) {
    unsigned h;
    asm("cvt.rn.bf16x2.f32 %0, %1, %2;" : "=r"(h) : "f"(x1), "f"(x0));
    float f0 = __uint_as_float(h << 16);
    float f1 = __uint_as_float(h & 0xffff0000u);
    float r0 = x0 - f0, r1 = x1 - f1;
    unsigned l;
    asm("cvt.rn.bf16x2.f32 %0, %1, %2;" : "=r"(l) : "f"(r1), "f"(r0));
    hi = h; lo = l;
}

__device__ __forceinline__ void cp16(unsigned short* smem_dst, const void* gsrc, int sz) {
    unsigned da = (unsigned)__cvta_generic_to_shared(smem_dst);
    asm volatile("cp.async.cg.shared.global [%0], [%1], 16, %2;"
                 :: "r"(da), "l"(gsrc), "r"(sz) : "memory");
}
#define CP_COMMIT() asm volatile("cp.async.commit_group;" ::: "memory")
#define CP_WAIT1()  asm volatile("cp.async.wait_group 1;" ::: "memory")
#define CP_WAIT0()  asm volatile("cp.async.wait_group 0;" ::: "memory")

// Launch 0: zero out+flags AND copy x -> z
__global__ void k_init_copy(float* __restrict__ out, const float4* __restrict__ x,
                            float4* __restrict__ z) {
    long long tid = (long long)blockIdx.x * blockDim.x + threadIdx.x;
    long long stride = (long long)gridDim.x * blockDim.x;
    if (tid < 2) g_flags[tid] = 0u;
    for (long long i = tid; i < NGRAPH * HID; i += stride) out[i] = 0.f;
    const long long n4 = (long long)NNODES * INC / 4;
    for (long long i = tid; i < n4; i += stride) z[i] = x[i];
}

// Launch 1: dtype detect AND weight pre-convert into chunk-interleaved pool
__global__ void k_detect_cvt(const unsigned* __restrict__ ei, const unsigned* __restrict__ ba,
                             const float* __restrict__ w1_0, const float* __restrict__ w2_0,
                             const float* __restrict__ w1s, const float* __restrict__ w2s) {
    long long stride = (long long)gridDim.x * blockDim.x;
    long long tid = (long long)blockIdx.x * blockDim.x + threadIdx.x;
    for (long long p = tid; p < WTOT_CP; p += stride) {
        const float* src;
        long long loc;
        if (p < W2_0_CP)     { src = w1_0; loc = p - W1_0_CP; }
        else if (p < W1S_CP) { src = w2_0; loc = p - W2_0_CP; }
        else if (p < W2S_CP) { src = w1s;  loc = p - W1S_CP; }
        else                 { src = w2s;  loc = p - W2S_CP; }
        float4 a = *(const float4*)(src + loc * 8);
        float4 b = *(const float4*)(src + loc * 8 + 4);
        uint4 hi, lo;
        cvt_hilo(a.x, a.y, hi.x, lo.x);
        cvt_hilo(a.z, a.w, hi.y, lo.y);
        cvt_hilo(b.x, b.y, hi.z, lo.z);
        cvt_hilo(b.z, b.w, hi.w, lo.w);
        g_w3[p * 2]     = hi;
        g_w3[p * 2 + 1] = lo;
    }
    unsigned acc = 0;
    for (long long w = 2 * tid + 1; w < 2LL * NEDGES; w += 2 * stride) acc |= ei[w];
    if (acc) atomicOr(&g_flags[0], 1u);
    acc = 0;
    for (long long w = 2 * tid + 1; w < NNODES; w += 2 * stride) acc |= ba[w];
    if (acc) atomicOr(&g_flags[1], 1u);
}

// Thread-per-(edge, float4-group) scatter (R7-proven form)
__global__ void k_scatter(const float* __restrict__ h, float* __restrict__ z,
                          const void* __restrict__ ei, int lg) {
    bool is64 = (g_flags[0] == 0u);
    long long total = (long long)NEDGES << lg;
    long long stride = (long long)gridDim.x * blockDim.x;
    long long mask = (1LL << lg) - 1;
    for (long long t = (long long)blockIdx.x * blockDim.x + threadIdx.x; t < total; t += stride) {
        long long e = t >> lg;
        int c = (int)(t & mask) * 4;
        int s = ld_idx(ei, e, is64);
        int d = ld_idx(ei, (long long)NEDGES + e, is64);
        const float4 v = *(const float4*)(h + ((long long)s << (lg + 2)) + c);
        float* dp = z + ((long long)d << (lg + 2)) + c;
        asm volatile("red.global.add.v4.f32 [%0], {%1,%2,%3,%4};"
                     :: "l"(dp), "f"(v.x), "f"(v.y), "f"(v.z), "f"(v.w) : "memory");
    }
}

// ---- GEMM core ----
#define GEMM_PROLOG                                                                  \
    extern __shared__ __align__(16) unsigned short dynsm[];                          \
    const int M = NNODES;                                                            \
    int tid = threadIdx.x;                                                           \
    int lane = tid & 31, warp = tid >> 5;                                            \
    int wm = (warp & 1) * 64, wn = (warp >> 1) * 32;                                 \
    int row0 = blockIdx.x * BM, col0 = blockIdx.y * BN;                              \
    float c[4][4][4];                                                                \
    _Pragma("unroll") for (int mt = 0; mt < 4; mt++)                                 \
        _Pragma("unroll") for (int nt = 0; nt < 4; nt++)                             \
            _Pragma("unroll") for (int i = 0; i < 4; i++) c[mt][nt][i] = 0.f;

// B tile via cp.async: rows kt..kt+31, 16 col-chunks at col0
#define STAGE_B3(W3, KT, S)                                                          \
    {                                                                                \
        unsigned short* Bh = dynsm + (S) * STAGE_SHORTS + BH_OFF;                    \
        unsigned short* Bl = dynsm + (S) * STAGE_SHORTS + BL_OFF;                    \
        _Pragma("unroll") for (int i = 0; i < 2; i++) {                              \
            int idx = tid * 2 + i;                                                   \
            int r = idx >> 4, jj = idx & 15;                                         \
            const uint4* src = (W3) + (((KT) + r) * 32 + (col0 >> 3) + jj) * 2;      \
            cp16(Bh + r * SB + jj * 8, src, 16);                                     \
            cp16(Bl + r * SB + jj * 8, src + 1, 16);                                 \
        }                                                                            \
    }

// A tile via cp.async from chunk-interleaved T3
#define STAGE_A3(T3, KT, S)                                                          \
    {                                                                                \
        unsigned short* Ah = dynsm + (S) * STAGE_SHORTS + AH_OFF;                    \
        unsigned short* Al = dynsm + (S) * STAGE_SHORTS + AL_OFF;                    \
        _Pragma("unroll") for (int i = 0; i < 2; i++) {                              \
            int idx = tid * 2 + i;                                                   \
            int r = idx >> 2, jj = idx & 3;                                          \
            int gr = row0 + r;                                                       \
            int sz = (gr < M) ? 16 : 0;                                              \
            if (gr >= M) gr = 0;                                                     \
            const uint4* src = (T3) + ((long long)gr * 32 + ((KT) >> 3) + jj) * 2;   \
            cp16(Ah + r * SA + jj * 8, src, sz);                                     \
            cp16(Al + r * SA + jj * 8, src + 1, sz);                                 \
        }                                                                            \
    }

// A tile fp32: load to regs (prefetch)
#define LDG_A1(A32, KT, PA)                                                          \
    _Pragma("unroll") for (int i = 0; i < 4; i++) {                                  \
        int lin = tid + i * 256;                                                     \
        int r = lin >> 3, q = lin & 7;                                               \
        int gr = row0 + r;                                                           \
        PA[i] = make_float4(0.f, 0.f, 0.f, 0.f);                                     \
        if (gr < M) PA[i] = *(const float4*)((A32) + (long long)gr * K + (KT) + q * 4); \
    }

// cvt + STS the prefetched fp32 A regs
#define STS_A1(PA, S)                                                                \
    {                                                                                \
        unsigned short* Ah = dynsm + (S) * STAGE_SHORTS + AH_OFF;                    \
        unsigned short* Al = dynsm + (S) * STAGE_SHORTS + AL_OFF;                    \
        _Pragma("unroll") for (int i = 0; i < 4; i++) {                              \
            int lin = tid + i * 256;                                                 \
            int r = lin >> 3, q = lin & 7;                                           \
            unsigned h0, l0, h1, l1;                                                 \
            cvt_hilo(PA[i].x, PA[i].y, h0, l0);                                      \
            cvt_hilo(PA[i].z, PA[i].w, h1, l1);                                      \
            *(uint2*)&Ah[r * SA + q * 4] = make_uint2(h0, h1);                       \
            *(uint2*)&Al[r * SA + q * 4] = make_uint2(l0, l1);                       \
        }                                                                            \
    }

#define GEMM_COMPUTE(S)                                                              \
    {                                                                                \
    const unsigned short* Ah = dynsm + (S) * STAGE_SHORTS + AH_OFF;                  \
    const unsigned short* Al = dynsm + (S) * STAGE_SHORTS + AL_OFF;                  \
    const unsigned short* Bh = dynsm + (S) * STAGE_SHORTS + BH_OFF;                  \
    const unsigned short* Bl = dynsm + (S) * STAGE_SHORTS + BL_OFF;                  \
    _Pragma("unroll") for (int kc = 0; kc < 2; kc++) {                               \
        unsigned ah[4][4], al[4][4], bh[4][2], bl[4][2];                             \
        int arow = lane & 15;                                                        \
        int acol = kc * 16 + (lane >> 4) * 8;                                        \
        _Pragma("unroll") for (int mt = 0; mt < 4; mt++) {                           \
            unsigned sa = (unsigned)__cvta_generic_to_shared(                        \
                &Ah[(wm + mt * 16 + arow) * SA + acol]);                             \
            asm volatile("ldmatrix.sync.aligned.m8n8.x4.shared.b16 {%0,%1,%2,%3}, [%4];" \
                         : "=r"(ah[mt][0]), "=r"(ah[mt][1]), "=r"(ah[mt][2]), "=r"(ah[mt][3]) \
                         : "r"(sa));                                                 \
            unsigned sb = (unsigned)__cvta_generic_to_shared(                        \
                &Al[(wm + mt * 16 + arow) * SA + acol]);                             \
            asm volatile("ldmatrix.sync.aligned.m8n8.x4.shared.b16 {%0,%1,%2,%3}, [%4];" \
                         : "=r"(al[mt][0]), "=r"(al[mt][1]), "=r"(al[mt][2]), "=r"(al[mt][3]) \
                         : "r"(sb));                                                 \
        }                                                                            \
        int brow = kc * 16 + (lane & 15);                                            \
        _Pragma("unroll") for (int nt2 = 0; nt2 < 2; nt2++) {                        \
            int bcol = wn + nt2 * 16 + (lane >> 4) * 8;                              \
            unsigned sh = (unsigned)__cvta_generic_to_shared(&Bh[brow * SB + bcol]); \
            asm volatile("ldmatrix.sync.aligned.m8n8.x4.trans.shared.b16 {%0,%1,%2,%3}, [%4];" \
                         : "=r"(bh[2 * nt2][0]), "=r"(bh[2 * nt2][1]),               \
                           "=r"(bh[2 * nt2 + 1][0]), "=r"(bh[2 * nt2 + 1][1])        \
                         : "r"(sh));                                                 \
            unsigned sl = (unsigned)__cvta_generic_to_shared(&Bl[brow * SB + bcol]); \
            asm volatile("ldmatrix.sync.aligned.m8n8.x4.trans.shared.b16 {%0,%1,%2,%3}, [%4];" \
                         : "=r"(bl[2 * nt2][0]), "=r"(bl[2 * nt2][1]),               \
                           "=r"(bl[2 * nt2 + 1][0]), "=r"(bl[2 * nt2 + 1][1])        \
                         : "r"(sl));                                                 \
        }                                                                            \
        _Pragma("unroll") for (int mt = 0; mt < 4; mt++)                             \
            _Pragma("unroll") for (int nt = 0; nt < 4; nt++) {                       \
                float* cc = c[mt][nt];                                               \
                MMA1(ah[mt], bh[nt], cc); MMA1(ah[mt], bl[nt], cc);                  \
                MMA1(al[mt], bh[nt], cc);                                            \
            }                                                                        \
    }                                                                                \
    }

#define MMA1(AREG, BREG, cc)                                                         \
    asm volatile("mma.sync.aligned.m16n8k16.row.col.f32.bf16.bf16.f32 "              \
                 "{%0,%1,%2,%3}, {%4,%5,%6,%7}, {%8,%9}, {%0,%1,%2,%3};"             \
                 : "+f"(cc[0]), "+f"(cc[1]), "+f"(cc[2]), "+f"(cc[3])                \
                 : "r"(AREG[0]), "r"(AREG[1]), "r"(AREG[2]), "r"(AREG[3]),           \
                   "r"(BREG[0]), "r"(BREG[1]))

// GEMM1: T3out = chunk_pack(relu(A32 @ W + bias)); A fp32 with reg-prefetch, B cp.async
__global__ void __launch_bounds__(256, 2)
k_gemm1(const float* __restrict__ A32, const uint4* __restrict__ W3,
        const float* __restrict__ bias, uint4* __restrict__ T3out, int K) {
    GEMM_PROLOG
    int nt = K / BK;
    float4 pa[4];
    LDG_A1(A32, 0, pa)
    STS_A1(pa, 0)
    STAGE_B3(W3, 0, 0)
    CP_COMMIT();
    for (int t = 0; t < nt; t++) {
        int s = t & 1;
        if (t + 1 < nt) {
            LDG_A1(A32, (t + 1) * BK, pa)
            STAGE_B3(W3, (t + 1) * BK, s ^ 1)
            CP_COMMIT();
            CP_WAIT1();
        } else {
            CP_WAIT0();
        }
        __syncthreads();
        GEMM_COMPUTE(s)
        if (t + 1 < nt) STS_A1(pa, s ^ 1)
        __syncthreads();
    }
    // epilogue -> chunk-interleaved T3
    unsigned* t3w = (unsigned*)T3out;
    int g = lane >> 2, tg = lane & 3;
#pragma unroll
    for (int nt2 = 0; nt2 < 4; nt2++) {
        int gcol = col0 + wn + nt2 * 8 + tg * 2;
        float b0 = bias[gcol], b1 = bias[gcol + 1];
        int word = (gcol >> 3) * 8 + ((gcol & 7) >> 1);
#pragma unroll
        for (int mt = 0; mt < 4; mt++) {
#pragma unroll
            for (int half = 0; half < 2; half++) {
                int rr = row0 + wm + mt * 16 + g + half * 8;
                if (rr < M) {
                    float ox = fmaxf(c[mt][nt2][half * 2 + 0] + b0, 0.f);
                    float oy = fmaxf(c[mt][nt2][half * 2 + 1] + b1, 0.f);
                    unsigned hp, lp;
                    cvt_hilo(ox, oy, hp, lp);
                    t3w[(long long)rr * 256 + word] = hp;
                    t3w[(long long)rr * 256 + word + 4] = lp;
                }
            }
        }
    }
}

// GEMM2: relu(T3 @ W + bias) -> fp32 C (+C2) or fused pool. A and B via cp.async.
__global__ void __launch_bounds__(256, 2)
k_gemm2(const uint4* __restrict__ T3, const uint4* __restrict__ W3,
        const float* __restrict__ bias, float* __restrict__ C,
        float* __restrict__ C2, float* __restrict__ pool_out,
        const void* __restrict__ ba, int K) {
    GEMM_PROLOG
    int nt = K / BK;
    STAGE_A3(T3, 0, 0)
    STAGE_B3(W3, 0, 0)
    CP_COMMIT();
    for (int t = 0; t < nt; t++) {
        int s = t & 1;
        if (t + 1 < nt) {
            STAGE_A3(T3, (t + 1) * BK, s ^ 1)
            STAGE_B3(W3, (t + 1) * BK, s ^ 1)
            CP_COMMIT();
            CP_WAIT1();
        } else {
            CP_WAIT0();
        }
        __syncthreads();
        GEMM_COMPUTE(s)
        __syncthreads();
    }
    bool is64b = (g_flags[1] == 0u);
    int g = lane >> 2, tg = lane & 3;
#pragma unroll
    for (int nt2 = 0; nt2 < 4; nt2++) {
        int gcol = col0 + wn + nt2 * 8 + tg * 2;
        float b0 = bias[gcol], b1 = bias[gcol + 1];
#pragma unroll
        for (int mt = 0; mt < 4; mt++) {
#pragma unroll
            for (int half = 0; half < 2; half++) {
                int rr = row0 + wm + mt * 16 + g + half * 8;
                if (rr < M) {
                    float2 o;
                    o.x = fmaxf(c[mt][nt2][half * 2 + 0] + b0, 0.f);
                    o.y = fmaxf(c[mt][nt2][half * 2 + 1] + b1, 0.f);
                    if (pool_out) {
                        int gb = ld_idx(ba, rr, is64b);
                        float* dp = pool_out + (long long)gb * HID + gcol;
                        asm volatile("red.global.add.v2.f32 [%0], {%1,%2};"
                                     :: "l"(dp), "f"(o.x), "f"(o.y) : "memory");
                    } else {
                        long long off = (long long)rr * HID + gcol;
                        *(float2*)(C + off) = o;
                        if (C2) *(float2*)(C2 + off) = o;
                    }
                }
            }
        }
    }
}

extern "C" void kernel_launch(void* const* d_in, const int* in_sizes, int n_in,
                              void* d_out, int out_size) {
    const float* x    = (const float*)d_in[0];
    const void*  ei   = d_in[1];
    const void*  ba   = d_in[2];
    const float* w1_0 = (const float*)d_in[3];
    const float* b1_0 = (const float*)d_in[4];
    const float* w2_0 = (const float*)d_in[5];
    const float* b2_0 = (const float*)d_in[6];
    const float* w1s  = (const float*)d_in[7];
    const float* b1s  = (const float*)d_in[8];
    const float* w2s  = (const float*)d_in[9];
    const float* b2s  = (const float*)d_in[10];
    float* out = (float*)d_out;

    float *z, *h;
    uint4 *t3, *w3;
    cudaGetSymbolAddress((void**)&z, g_z);
    cudaGetSymbolAddress((void**)&h, g_h);
    cudaGetSymbolAddress((void**)&t3, g_t3);
    cudaGetSymbolAddress((void**)&w3, g_w3);

    const int SMEM = 2 * STAGE_SHORTS * 2;  // 75776 bytes
    cudaFuncSetAttribute(k_gemm1, cudaFuncAttributeMaxDynamicSharedMemorySize, SMEM);
    cudaFuncSetAttribute(k_gemm2, cudaFuncAttributeMaxDynamicSharedMemorySize, SMEM);

    dim3 ggrid((NNODES + BM - 1) / BM, HID / BN);  // (391, 2)

    // ncu captures launch index 3 -> k_gemm1 (layer 0).
    k_init_copy<<<2048, 256>>>(out, (const float4*)x, (float4*)z);              // 0
    k_detect_cvt<<<960, 256>>>((const unsigned*)ei, (const unsigned*)ba,        // 1
                               w1_0, w2_0, w1s, w2s);
    k_scatter<<<4736, 256>>>(x, z, ei, 5);                                      // 2
    k_gemm1<<<ggrid, 256, SMEM>>>(z, w3 + W1_0_CP * 2, b1_0, t3, INC);          // 3 <- profiled
    k_gemm2<<<ggrid, 256, SMEM>>>(t3, w3 + W2_0_CP * 2, b2_0, h, z, nullptr, nullptr, HID);

    for (int l = 0; l < 3; l++) {
        k_scatter<<<4736, 256>>>(h, z, ei, 6);
        k_gemm1<<<ggrid, 256, SMEM>>>(z, w3 + (W1S_CP + l * 8192) * 2, b1s + l * HID, t3, HID);
        if (l < 2) {
            k_gemm2<<<ggrid, 256, SMEM>>>(t3, w3 + (W2S_CP + l * 8192) * 2, b2s + l * HID,
                                          h, z, nullptr, nullptr, HID);
        } else {
            k_gemm2<<<ggrid, 256, SMEM>>>(t3, w3 + (W2S_CP + l * 8192) * 2, b2s + l * HID,
                                          nullptr, nullptr, out, ba, HID);
        }
    }
}

// round 11
// speedup vs baseline: 1.1330x; 1.1330x over previous
#include <cuda_runtime.h>
#include <cuda_bf16.h>
#include <cstdint>

#define NNODES 50000
#define NEDGES 800000
#define NGRAPH 256
#define INC    128
#define HID    256

#define BM 128
#define BN 128
#define BK 64
#define SA 72     // A smem row stride (shorts): 64 + 8 pad (144B = 9*16)
#define SB 136    // B smem row stride (shorts): 128 + 8 pad (272B = 17*16)

// Dynamic smem layout (shorts offsets)
#define AH_OFF 0                    // 128*72
#define AL_OFF (BM * SA)            // 9216
#define BH_OFF (2 * BM * SA)        // 18432
#define BL_OFF (2 * BM * SA + BK * SB)
#define SMEM_SHORTS (2 * BM * SA + 2 * BK * SB)   // 35840 shorts = 71680 B

// Packed-weight pool offsets (uint2 pairs; one pair = 2 columns hi+lo)
#define W1_0_P 0
#define W2_0_P 16384
#define W1S_P  49152
#define W2S_P  147456
#define WTOT_P 245760

static __device__ __align__(16) float g_z[(size_t)NNODES * HID];
static __device__ __align__(16) float g_h[(size_t)NNODES * HID];
static __device__ __align__(16) uint2 g_t2[(size_t)NNODES * 128];
static __device__ __align__(16) uint2 g_w2[WTOT_P];
static __device__ unsigned g_flags[2];

__device__ __forceinline__ int ld_idx(const void* p, long long i, bool is64) {
    if (is64) return (int)__ldg(&((const long long*)p)[i]);
    return __ldg(&((const int*)p)[i]);
}

__device__ __forceinline__ void cvt_hilo(float x0, float x1, unsigned& hi, unsigned& lo) {
    unsigned h;
    asm("cvt.rn.bf16x2.f32 %0, %1, %2;" : "=r"(h) : "f"(x1), "f"(x0));
    float f0 = __uint_as_float(h << 16);
    float f1 = __uint_as_float(h & 0xffff0000u);
    float r0 = x0 - f0, r1 = x1 - f1;
    unsigned l;
    asm("cvt.rn.bf16x2.f32 %0, %1, %2;" : "=r"(l) : "f"(r1), "f"(r0));
    hi = h; lo = l;
}

// Launch 0: zero out+flags AND copy x -> z
__global__ void k_init_copy(float* __restrict__ out, const float4* __restrict__ x,
                            float4* __restrict__ z) {
    long long tid = (long long)blockIdx.x * blockDim.x + threadIdx.x;
    long long stride = (long long)gridDim.x * blockDim.x;
    if (tid < 2) g_flags[tid] = 0u;
    for (long long i = tid; i < NGRAPH * HID; i += stride) out[i] = 0.f;
    const long long n4 = (long long)NNODES * INC / 4;
    for (long long i = tid; i < n4; i += stride) z[i] = x[i];
}

// Launch 1: dtype detect AND weight pre-convert
__global__ void k_detect_cvt(const unsigned* __restrict__ ei, const unsigned* __restrict__ ba,
                             const float* __restrict__ w1_0, const float* __restrict__ w2_0,
                             const float* __restrict__ w1s, const float* __restrict__ w2s) {
    long long stride = (long long)gridDim.x * blockDim.x;
    long long tid = (long long)blockIdx.x * blockDim.x + threadIdx.x;
    for (long long j = tid; j < WTOT_P; j += stride) {
        const float* src;
        long long off;
        if (j < W2_0_P)      { src = w1_0; off = j - W1_0_P; }
        else if (j < W1S_P)  { src = w2_0; off = j - W2_0_P; }
        else if (j < W2S_P)  { src = w1s;  off = j - W1S_P; }
        else                 { src = w2s;  off = j - W2S_P; }
        float2 v = *(const float2*)(src + 2 * off);
        unsigned hp, lp;
        cvt_hilo(v.x, v.y, hp, lp);
        g_w2[j] = make_uint2(hp, lp);
    }
    unsigned acc = 0;
    for (long long w = 2 * tid + 1; w < 2LL * NEDGES; w += 2 * stride) acc |= ei[w];
    if (acc) atomicOr(&g_flags[0], 1u);
    acc = 0;
    for (long long w = 2 * tid + 1; w < NNODES; w += 2 * stride) acc |= ba[w];
    if (acc) atomicOr(&g_flags[1], 1u);
}

// Thread-per-(edge, float4-group) scatter (R7-proven form)
__global__ void k_scatter(const float* __restrict__ h, float* __restrict__ z,
                          const void* __restrict__ ei, int lg) {
    bool is64 = (g_flags[0] == 0u);
    long long total = (long long)NEDGES << lg;
    long long stride = (long long)gridDim.x * blockDim.x;
    long long mask = (1LL << lg) - 1;
    for (long long t = (long long)blockIdx.x * blockDim.x + threadIdx.x; t < total; t += stride) {
        long long e = t >> lg;
        int c = (int)(t & mask) * 4;
        int s = ld_idx(ei, e, is64);
        int d = ld_idx(ei, (long long)NEDGES + e, is64);
        const float4 v = *(const float4*)(h + ((long long)s << (lg + 2)) + c);
        float* dp = z + ((long long)d << (lg + 2)) + c;
        asm volatile("red.global.add.v4.f32 [%0], {%1,%2,%3,%4};"
                     :: "l"(dp), "f"(v.x), "f"(v.y), "f"(v.z), "f"(v.w) : "memory");
    }
}

// ---- GEMM core ----
#define GEMM_PROLOG                                                                  \
    extern __shared__ __align__(16) unsigned short dynsm[];                          \
    unsigned short* Ah = dynsm + AH_OFF;                                             \
    unsigned short* Al = dynsm + AL_OFF;                                             \
    unsigned short* Bh = dynsm + BH_OFF;                                             \
    unsigned short* Bl = dynsm + BL_OFF;                                             \
    const int M = NNODES;                                                            \
    int tid = threadIdx.x;                                                           \
    int lane = tid & 31, warp = tid >> 5;                                            \
    int wm = (warp & 1) * 64, wn = (warp >> 1) * 32;                                 \
    int row0 = blockIdx.x * BM, col0 = blockIdx.y * BN;                              \
    float c[4][4][4];                                                                \
    _Pragma("unroll") for (int mt = 0; mt < 4; mt++)                                 \
        _Pragma("unroll") for (int nt = 0; nt < 4; nt++)                             \
            _Pragma("unroll") for (int i = 0; i < 4; i++) c[mt][nt][i] = 0.f;

// B tile: 64 rows x 128 cols from packed pool (uint4 = 2 uint2 = 4 cols)
#define STAGE_B_PACKED(W2, KT)                                                       \
    _Pragma("unroll") for (int i = 0; i < 8; i++) {                                  \
        int lin = tid + i * 256;                                                     \
        int r = lin >> 5, q = lin & 31;                                              \
        uint4 v = *(const uint4*)((W2) + ((KT) + r) * 128 + (col0 >> 1) + q * 2);    \
        *(uint2*)&Bh[r * SB + q * 4] = make_uint2(v.x, v.z);                         \
        *(uint2*)&Bl[r * SB + q * 4] = make_uint2(v.y, v.w);                         \
    }

#define GEMM_COMPUTE                                                                 \
    _Pragma("unroll") for (int kc = 0; kc < 4; kc++) {                               \
        unsigned ah[4][4], al[4][4], bh[4][2], bl[4][2];                             \
        int arow = lane & 15;                                                        \
        int acol = kc * 16 + (lane >> 4) * 8;                                        \
        _Pragma("unroll") for (int mt = 0; mt < 4; mt++) {                           \
            unsigned sa = (unsigned)__cvta_generic_to_shared(                        \
                &Ah[(wm + mt * 16 + arow) * SA + acol]);                             \
            asm volatile("ldmatrix.sync.aligned.m8n8.x4.shared.b16 {%0,%1,%2,%3}, [%4];" \
                         : "=r"(ah[mt][0]), "=r"(ah[mt][1]), "=r"(ah[mt][2]), "=r"(ah[mt][3]) \
                         : "r"(sa));                                                 \
            unsigned sb = (unsigned)__cvta_generic_to_shared(                        \
                &Al[(wm + mt * 16 + arow) * SA + acol]);                             \
            asm volatile("ldmatrix.sync.aligned.m8n8.x4.shared.b16 {%0,%1,%2,%3}, [%4];" \
                         : "=r"(al[mt][0]), "=r"(al[mt][1]), "=r"(al[mt][2]), "=r"(al[mt][3]) \
                         : "r"(sb));                                                 \
        }                                                                            \
        int brow = kc * 16 + (lane & 15);                                            \
        _Pragma("unroll") for (int nt2 = 0; nt2 < 2; nt2++) {                        \
            int bcol = wn + nt2 * 16 + (lane >> 4) * 8;                              \
            unsigned sh = (unsigned)__cvta_generic_to_shared(&Bh[brow * SB + bcol]); \
            asm volatile("ldmatrix.sync.aligned.m8n8.x4.trans.shared.b16 {%0,%1,%2,%3}, [%4];" \
                         : "=r"(bh[2 * nt2][0]), "=r"(bh[2 * nt2][1]),               \
                           "=r"(bh[2 * nt2 + 1][0]), "=r"(bh[2 * nt2 + 1][1])        \
                         : "r"(sh));                                                 \
            unsigned sl = (unsigned)__cvta_generic_to_shared(&Bl[brow * SB + bcol]); \
            asm volatile("ldmatrix.sync.aligned.m8n8.x4.trans.shared.b16 {%0,%1,%2,%3}, [%4];" \
                         : "=r"(bl[2 * nt2][0]), "=r"(bl[2 * nt2][1]),               \
                           "=r"(bl[2 * nt2 + 1][0]), "=r"(bl[2 * nt2 + 1][1])        \
                         : "r"(sl));                                                 \
        }                                                                            \
        _Pragma("unroll") for (int mt = 0; mt < 4; mt++)                             \
            _Pragma("unroll") for (int nt = 0; nt < 4; nt++) {                       \
                float* cc = c[mt][nt];                                               \
                MMA1(ah[mt], bh[nt], cc); MMA1(ah[mt], bl[nt], cc);                  \
                MMA1(al[mt], bh[nt], cc);                                            \
            }                                                                        \
    }

#define MMA1(AREG, BREG, cc)                                                         \
    asm volatile("mma.sync.aligned.m16n8k16.row.col.f32.bf16.bf16.f32 "              \
                 "{%0,%1,%2,%3}, {%4,%5,%6,%7}, {%8,%9}, {%0,%1,%2,%3};"             \
                 : "+f"(cc[0]), "+f"(cc[1]), "+f"(cc[2]), "+f"(cc[3])                \
                 : "r"(AREG[0]), "r"(AREG[1]), "r"(AREG[2]), "r"(AREG[3]),           \
                   "r"(BREG[0]), "r"(BREG[1]))

// GEMM1: t2 = pack_hilo(relu(A32 @ W + bias))
__global__ void __launch_bounds__(256, 2)
k_gemm1(const float* __restrict__ A32, const uint2* __restrict__ W2,
        const float* __restrict__ bias, uint2* __restrict__ T2, int K) {
    GEMM_PROLOG
    for (int kt = 0; kt < K; kt += BK) {
        // A: 128 rows x 64 cols fp32 -> hi/lo  (2048 float4, 8 per thread)
#pragma unroll
        for (int i = 0; i < 8; i++) {
            int lin = tid + i * 256;
            int r = lin >> 4, q = lin & 15;
            int gr = row0 + r;
            float4 v = make_float4(0.f, 0.f, 0.f, 0.f);
            if (gr < M) v = *(const float4*)(A32 + (long long)gr * K + kt + q * 4);
            unsigned h0, l0, h1, l1;
            cvt_hilo(v.x, v.y, h0, l0);
            cvt_hilo(v.z, v.w, h1, l1);
            *(uint2*)&Ah[r * SA + q * 4] = make_uint2(h0, h1);
            *(uint2*)&Al[r * SA + q * 4] = make_uint2(l0, l1);
        }
        STAGE_B_PACKED(W2, kt)
        __syncthreads();
        GEMM_COMPUTE
        __syncthreads();
    }
    int g = lane >> 2, tg = lane & 3;
#pragma unroll
    for (int nt = 0; nt < 4; nt++) {
        int gcol = col0 + wn + nt * 8 + tg * 2;
        float b0 = bias[gcol], b1 = bias[gcol + 1];
#pragma unroll
        for (int mt = 0; mt < 4; mt++) {
#pragma unroll
            for (int half = 0; half < 2; half++) {
                int rr = row0 + wm + mt * 16 + g + half * 8;
                if (rr < M) {
                    float ox = fmaxf(c[mt][nt][half * 2 + 0] + b0, 0.f);
                    float oy = fmaxf(c[mt][nt][half * 2 + 1] + b1, 0.f);
                    unsigned hp, lp;
                    cvt_hilo(ox, oy, hp, lp);
                    T2[(long long)rr * 128 + (gcol >> 1)] = make_uint2(hp, lp);
                }
            }
        }
    }
}

// GEMM2: relu(T2 @ W + bias) -> fp32 C (+C2) or fused global_add_pool
__global__ void __launch_bounds__(256, 2)
k_gemm2(const uint2* __restrict__ T2, const uint2* __restrict__ W2,
        const float* __restrict__ bias, float* __restrict__ C,
        float* __restrict__ C2, float* __restrict__ pool_out,
        const void* __restrict__ ba, int K) {
    GEMM_PROLOG
    for (int kt = 0; kt < K; kt += BK) {
        // A: 128 rows x 64 cols from packed T2 (uint4 = 4 cols), 8 per thread
#pragma unroll
        for (int i = 0; i < 8; i++) {
            int lin = tid + i * 256;
            int r = lin >> 4, q = lin & 15;
            int gr = row0 + r;
            uint4 v = make_uint4(0u, 0u, 0u, 0u);
            if (gr < M) v = *(const uint4*)(T2 + (long long)gr * 128 + ((kt + q * 4) >> 1));
            *(uint2*)&Ah[r * SA + q * 4] = make_uint2(v.x, v.z);
            *(uint2*)&Al[r * SA + q * 4] = make_uint2(v.y, v.w);
        }
        STAGE_B_PACKED(W2, kt)
        __syncthreads();
        GEMM_COMPUTE
        __syncthreads();
    }
    bool is64b = (g_flags[1] == 0u);
    int g = lane >> 2, tg = lane & 3;
#pragma unroll
    for (int nt = 0; nt < 4; nt++) {
        int gcol = col0 + wn + nt * 8 + tg * 2;
        float b0 = bias[gcol], b1 = bias[gcol + 1];
#pragma unroll
        for (int mt = 0; mt < 4; mt++) {
#pragma unroll
            for (int half = 0; half < 2; half++) {
                int rr = row0 + wm + mt * 16 + g + half * 8;
                if (rr < M) {
                    float2 o;
                    o.x = fmaxf(c[mt][nt][half * 2 + 0] + b0, 0.f);
                    o.y = fmaxf(c[mt][nt][half * 2 + 1] + b1, 0.f);
                    if (pool_out) {
                        int gb = ld_idx(ba, rr, is64b);
                        float* dp = pool_out + (long long)gb * HID + gcol;
                        asm volatile("red.global.add.v2.f32 [%0], {%1,%2};"
                                     :: "l"(dp), "f"(o.x), "f"(o.y) : "memory");
                    } else {
                        long long off = (long long)rr * HID + gcol;
                        *(float2*)(C + off) = o;
                        if (C2) *(float2*)(C2 + off) = o;
                    }
                }
            }
        }
    }
}

extern "C" void kernel_launch(void* const* d_in, const int* in_sizes, int n_in,
                              void* d_out, int out_size) {
    const float* x    = (const float*)d_in[0];
    const void*  ei   = d_in[1];
    const void*  ba   = d_in[2];
    const float* w1_0 = (const float*)d_in[3];
    const float* b1_0 = (const float*)d_in[4];
    const float* w2_0 = (const float*)d_in[5];
    const float* b2_0 = (const float*)d_in[6];
    const float* w1s  = (const float*)d_in[7];
    const float* b1s  = (const float*)d_in[8];
    const float* w2s  = (const float*)d_in[9];
    const float* b2s  = (const float*)d_in[10];
    float* out = (float*)d_out;

    float *z, *h;
    uint2 *t2, *w2;
    cudaGetSymbolAddress((void**)&z, g_z);
    cudaGetSymbolAddress((void**)&h, g_h);
    cudaGetSymbolAddress((void**)&t2, g_t2);
    cudaGetSymbolAddress((void**)&w2, g_w2);

    const int SMEM = SMEM_SHORTS * 2;  // 71680 bytes
    cudaFuncSetAttribute(k_gemm1, cudaFuncAttributeMaxDynamicSharedMemorySize, SMEM);
    cudaFuncSetAttribute(k_gemm2, cudaFuncAttributeMaxDynamicSharedMemorySize, SMEM);

    dim3 ggrid((NNODES + BM - 1) / BM, HID / BN);  // (391, 2)

    // ncu captures launch index 3 -> k_gemm1 (layer 0).
    k_init_copy<<<2048, 256>>>(out, (const float4*)x, (float4*)z);              // 0
    k_detect_cvt<<<960, 256>>>((const unsigned*)ei, (const unsigned*)ba,        // 1
                               w1_0, w2_0, w1s, w2s);
    k_scatter<<<4736, 256>>>(x, z, ei, 5);                                      // 2
    k_gemm1<<<ggrid, 256, SMEM>>>(z, w2 + W1_0_P, b1_0, t2, INC);               // 3 <- profiled
    k_gemm2<<<ggrid, 256, SMEM>>>(t2, w2 + W2_0_P, b2_0, h, z, nullptr, nullptr, HID);

    for (int l = 0; l < 3; l++) {
        k_scatter<<<4736, 256>>>(h, z, ei, 6);
        k_gemm1<<<ggrid, 256, SMEM>>>(z, w2 + W1S_P + l * (HID * HID / 2), b1s + l * HID, t2, HID);
        if (l < 2) {
            k_gemm2<<<ggrid, 256, SMEM>>>(t2, w2 + W2S_P + l * (HID * HID / 2), b2s + l * HID,
                                          h, z, nullptr, nullptr, HID);
        } else {
            k_gemm2<<<ggrid, 256, SMEM>>>(t2, w2 + W2S_P + l * (HID * HID / 2), b2s + l * HID,
                                          nullptr, nullptr, out, ba, HID);
        }
    }
}

// round 12
// speedup vs baseline: 1.1572x; 1.0213x over previous
#include <cuda_runtime.h>
#include <cuda_bf16.h>
#include <cstdint>

#define NNODES 50000
#define NEDGES 800000
#define NGRAPH 256
#define INC    128
#define HID    256

#define BM 128
#define BN 128
#define BK 32
#define SA 40

// Fragment-layout weight pool (uint4 units). Per weight [K,256]:
// (K/16) kt-tiles x 32 n8-tiles x 32 lanes, uint4 = {b0h,b1h,b0l,b1l}
#define W1_0_F 0
#define W2_0_F 8192
#define W1S_F  24576      // + l*16384
#define W2S_F  73728      // + l*16384
#define WTOT_F 122880

static __device__ __align__(16) float g_z[(size_t)NNODES * HID];
static __device__ __align__(16) float g_h[(size_t)NNODES * HID];
static __device__ __align__(16) uint2 g_t2[(size_t)NNODES * 128];
static __device__ __align__(16) uint4 g_wf[WTOT_F];
static __device__ unsigned g_flags[2];

__device__ __forceinline__ int ld_idx(const void* p, long long i, bool is64) {
    if (is64) return (int)__ldg(&((const long long*)p)[i]);
    return __ldg(&((const int*)p)[i]);
}

__device__ __forceinline__ void cvt_hilo(float x0, float x1, unsigned& hi, unsigned& lo) {
    unsigned h;
    asm("cvt.rn.bf16x2.f32 %0, %1, %2;" : "=r"(h) : "f"(x1), "f"(x0));
    float f0 = __uint_as_float(h << 16);
    float f1 = __uint_as_float(h & 0xffff0000u);
    float r0 = x0 - f0, r1 = x1 - f1;
    unsigned l;
    asm("cvt.rn.bf16x2.f32 %0, %1, %2;" : "=r"(l) : "f"(r1), "f"(r0));
    hi = h; lo = l;
}

// Launch 0: zero out+flags AND copy x -> z
__global__ void k_init_copy(float* __restrict__ out, const float4* __restrict__ x,
                            float4* __restrict__ z) {
    long long tid = (long long)blockIdx.x * blockDim.x + threadIdx.x;
    long long stride = (long long)gridDim.x * blockDim.x;
    if (tid < 2) g_flags[tid] = 0u;
    for (long long i = tid; i < NGRAPH * HID; i += stride) out[i] = 0.f;
    const long long n4 = (long long)NNODES * INC / 4;
    for (long long i = tid; i < n4; i += stride) z[i] = x[i];
}

// Launch 1: dtype detect AND weight pre-convert into MMA B-fragment layout.
// For uint4 index u in a weight [K,256]: kt=u>>10, n8=(u>>5)&31, lane=u&31;
// n = n8*8 + (lane>>2); k0 = kt*16 + (lane&3)*2; elements (k0,k0+1,k0+8,k0+9).
__global__ void k_detect_cvt(const unsigned* __restrict__ ei, const unsigned* __restrict__ ba,
                             const float* __restrict__ w1_0, const float* __restrict__ w2_0,
                             const float* __restrict__ w1s, const float* __restrict__ w2s) {
    long long stride = (long long)gridDim.x * blockDim.x;
    long long tid = (long long)blockIdx.x * blockDim.x + threadIdx.x;
    for (long long j = tid; j < WTOT_F; j += stride) {
        const float* src;
        int u;
        if (j < W2_0_F)      { src = w1_0; u = (int)j; }
        else if (j < W1S_F)  { src = w2_0; u = (int)(j - W2_0_F); }
        else if (j < W2S_F)  { int loc = (int)(j - W1S_F); src = w1s + (loc / 16384) * (HID * HID); u = loc % 16384; }
        else                 { int loc = (int)(j - W2S_F); src = w2s + (loc / 16384) * (HID * HID); u = loc % 16384; }
        int kt = u >> 10, n8 = (u >> 5) & 31, lane = u & 31;
        int n = n8 * 8 + (lane >> 2);
        int k0 = kt * 16 + (lane & 3) * 2;
        float a = __ldg(&src[(long long)k0 * HID + n]);
        float b = __ldg(&src[(long long)(k0 + 1) * HID + n]);
        float c = __ldg(&src[(long long)(k0 + 8) * HID + n]);
        float d = __ldg(&src[(long long)(k0 + 9) * HID + n]);
        unsigned h01, l01, h89, l89;
        cvt_hilo(a, b, h01, l01);
        cvt_hilo(c, d, h89, l89);
        g_wf[j] = make_uint4(h01, h89, l01, l89);
    }
    unsigned acc = 0;
    for (long long w = 2 * tid + 1; w < 2LL * NEDGES; w += 2 * stride) acc |= ei[w];
    if (acc) atomicOr(&g_flags[0], 1u);
    acc = 0;
    for (long long w = 2 * tid + 1; w < NNODES; w += 2 * stride) acc |= ba[w];
    if (acc) atomicOr(&g_flags[1], 1u);
}

// Thread-per-(edge, float4-group) scatter (proven form)
__global__ void k_scatter(const float* __restrict__ h, float* __restrict__ z,
                          const void* __restrict__ ei, int lg) {
    bool is64 = (g_flags[0] == 0u);
    long long total = (long long)NEDGES << lg;
    long long stride = (long long)gridDim.x * blockDim.x;
    long long mask = (1LL << lg) - 1;
    for (long long t = (long long)blockIdx.x * blockDim.x + threadIdx.x; t < total; t += stride) {
        long long e = t >> lg;
        int c = (int)(t & mask) * 4;
        int s = ld_idx(ei, e, is64);
        int d = ld_idx(ei, (long long)NEDGES + e, is64);
        const float4 v = *(const float4*)(h + ((long long)s << (lg + 2)) + c);
        float* dp = z + ((long long)d << (lg + 2)) + c;
        asm volatile("red.global.add.v4.f32 [%0], {%1,%2,%3,%4};"
                     :: "l"(dp), "f"(v.x), "f"(v.y), "f"(v.z), "f"(v.w) : "memory");
    }
}

// ---- GEMM core: A via smem+ldmatrix, B via direct fragment LDG.128 ----
#define GEMM_PROLOG                                                                  \
    __shared__ __align__(16) unsigned short Ah[BM * SA];                             \
    __shared__ __align__(16) unsigned short Al[BM * SA];                             \
    const int M = NNODES;                                                            \
    int tid = threadIdx.x;                                                           \
    int lane = tid & 31, warp = tid >> 5;                                            \
    int wm = (warp & 1) * 64, wn = (warp >> 1) * 32;                                 \
    int row0 = blockIdx.x * BM, col0 = blockIdx.y * BN;                              \
    int n8base = (col0 + wn) >> 3;                                                   \
    float c[4][4][4];                                                                \
    _Pragma("unroll") for (int mt = 0; mt < 4; mt++)                                 \
        _Pragma("unroll") for (int nt = 0; nt < 4; nt++)                             \
            _Pragma("unroll") for (int i = 0; i < 4; i++) c[mt][nt][i] = 0.f;

#define GEMM_COMPUTE(Wf, KT)                                                         \
    _Pragma("unroll") for (int kc = 0; kc < 2; kc++) {                               \
        unsigned ah[4][4], al[4][4], bh[4][2], bl[4][2];                             \
        int ktile = ((KT) >> 4) + kc;                                                \
        _Pragma("unroll") for (int nt = 0; nt < 4; nt++) {                           \
            uint4 q = __ldg((Wf) + (ktile * 32 + n8base + nt) * 32 + lane);          \
            bh[nt][0] = q.x; bh[nt][1] = q.y;                                        \
            bl[nt][0] = q.z; bl[nt][1] = q.w;                                        \
        }                                                                            \
        int arow = lane & 15;                                                        \
        int acol = kc * 16 + (lane >> 4) * 8;                                        \
        _Pragma("unroll") for (int mt = 0; mt < 4; mt++) {                           \
            unsigned sa = (unsigned)__cvta_generic_to_shared(                        \
                &Ah[(wm + mt * 16 + arow) * SA + acol]);                             \
            asm volatile("ldmatrix.sync.aligned.m8n8.x4.shared.b16 {%0,%1,%2,%3}, [%4];" \
                         : "=r"(ah[mt][0]), "=r"(ah[mt][1]), "=r"(ah[mt][2]), "=r"(ah[mt][3]) \
                         : "r"(sa));                                                 \
            unsigned sb = (unsigned)__cvta_generic_to_shared(                        \
                &Al[(wm + mt * 16 + arow) * SA + acol]);                             \
            asm volatile("ldmatrix.sync.aligned.m8n8.x4.shared.b16 {%0,%1,%2,%3}, [%4];" \
                         : "=r"(al[mt][0]), "=r"(al[mt][1]), "=r"(al[mt][2]), "=r"(al[mt][3]) \
                         : "r"(sb));                                                 \
        }                                                                            \
        _Pragma("unroll") for (int mt = 0; mt < 4; mt++)                             \
            _Pragma("unroll") for (int nt = 0; nt < 4; nt++) {                       \
                float* cc = c[mt][nt];                                               \
                MMA1(ah[mt], bh[nt], cc); MMA1(ah[mt], bl[nt], cc);                  \
                MMA1(al[mt], bh[nt], cc);                                            \
            }                                                                        \
    }

#define MMA1(AREG, BREG, cc)                                                         \
    asm volatile("mma.sync.aligned.m16n8k16.row.col.f32.bf16.bf16.f32 "              \
                 "{%0,%1,%2,%3}, {%4,%5,%6,%7}, {%8,%9}, {%0,%1,%2,%3};"             \
                 : "+f"(cc[0]), "+f"(cc[1]), "+f"(cc[2]), "+f"(cc[3])                \
                 : "r"(AREG[0]), "r"(AREG[1]), "r"(AREG[2]), "r"(AREG[3]),           \
                   "r"(BREG[0]), "r"(BREG[1]))

// GEMM1: t2 = pack_hilo(relu(A32 @ W + bias))
__global__ void __launch_bounds__(256, 2)
k_gemm1(const float* __restrict__ A32, const uint4* __restrict__ Wf,
        const float* __restrict__ bias, uint2* __restrict__ T2, int K) {
    GEMM_PROLOG
    for (int kt = 0; kt < K; kt += BK) {
#pragma unroll
        for (int i = 0; i < 4; i++) {
            int lin = tid + i * 256;
            int r = lin >> 3, q = lin & 7;
            int gr = row0 + r;
            float4 v = make_float4(0.f, 0.f, 0.f, 0.f);
            if (gr < M) v = *(const float4*)(A32 + (long long)gr * K + kt + q * 4);
            unsigned h0, l0, h1, l1;
            cvt_hilo(v.x, v.y, h0, l0);
            cvt_hilo(v.z, v.w, h1, l1);
            *(uint2*)&Ah[r * SA + q * 4] = make_uint2(h0, h1);
            *(uint2*)&Al[r * SA + q * 4] = make_uint2(l0, l1);
        }
        __syncthreads();
        GEMM_COMPUTE(Wf, kt)
        __syncthreads();
    }
    int g = lane >> 2, tg = lane & 3;
#pragma unroll
    for (int nt = 0; nt < 4; nt++) {
        int gcol = col0 + wn + nt * 8 + tg * 2;
        float b0 = bias[gcol], b1 = bias[gcol + 1];
#pragma unroll
        for (int mt = 0; mt < 4; mt++) {
#pragma unroll
            for (int half = 0; half < 2; half++) {
                int rr = row0 + wm + mt * 16 + g + half * 8;
                if (rr < M) {
                    float ox = fmaxf(c[mt][nt][half * 2 + 0] + b0, 0.f);
                    float oy = fmaxf(c[mt][nt][half * 2 + 1] + b1, 0.f);
                    unsigned hp, lp;
                    cvt_hilo(ox, oy, hp, lp);
                    T2[(long long)rr * 128 + (gcol >> 1)] = make_uint2(hp, lp);
                }
            }
        }
    }
}

// GEMM2: relu(T2 @ W + bias) -> fp32 C (+C2) or fused global_add_pool
__global__ void __launch_bounds__(256, 2)
k_gemm2(const uint2* __restrict__ T2, const uint4* __restrict__ Wf,
        const float* __restrict__ bias, float* __restrict__ C,
        float* __restrict__ C2, float* __restrict__ pool_out,
        const void* __restrict__ ba, int K) {
    GEMM_PROLOG
    for (int kt = 0; kt < K; kt += BK) {
#pragma unroll
        for (int i = 0; i < 4; i++) {
            int lin = tid + i * 256;
            int r = lin >> 3, q = lin & 7;
            int gr = row0 + r;
            uint4 v = make_uint4(0u, 0u, 0u, 0u);
            if (gr < M) v = *(const uint4*)(T2 + (long long)gr * 128 + ((kt + q * 4) >> 1));
            *(uint2*)&Ah[r * SA + q * 4] = make_uint2(v.x, v.z);
            *(uint2*)&Al[r * SA + q * 4] = make_uint2(v.y, v.w);
        }
        __syncthreads();
        GEMM_COMPUTE(Wf, kt)
        __syncthreads();
    }
    bool is64b = (g_flags[1] == 0u);
    int g = lane >> 2, tg = lane & 3;
#pragma unroll
    for (int nt = 0; nt < 4; nt++) {
        int gcol = col0 + wn + nt * 8 + tg * 2;
        float b0 = bias[gcol], b1 = bias[gcol + 1];
#pragma unroll
        for (int mt = 0; mt < 4; mt++) {
#pragma unroll
            for (int half = 0; half < 2; half++) {
                int rr = row0 + wm + mt * 16 + g + half * 8;
                if (rr < M) {
                    float2 o;
                    o.x = fmaxf(c[mt][nt][half * 2 + 0] + b0, 0.f);
                    o.y = fmaxf(c[mt][nt][half * 2 + 1] + b1, 0.f);
                    if (pool_out) {
                        int gb = ld_idx(ba, rr, is64b);
                        float* dp = pool_out + (long long)gb * HID + gcol;
                        asm volatile("red.global.add.v2.f32 [%0], {%1,%2};"
                                     :: "l"(dp), "f"(o.x), "f"(o.y) : "memory");
                    } else {
                        long long off = (long long)rr * HID + gcol;
                        *(float2*)(C + off) = o;
                        if (C2) *(float2*)(C2 + off) = o;
                    }
                }
            }
        }
    }
}

extern "C" void kernel_launch(void* const* d_in, const int* in_sizes, int n_in,
                              void* d_out, int out_size) {
    const float* x    = (const float*)d_in[0];
    const void*  ei   = d_in[1];
    const void*  ba   = d_in[2];
    const float* w1_0 = (const float*)d_in[3];
    const float* b1_0 = (const float*)d_in[4];
    const float* w2_0 = (const float*)d_in[5];
    const float* b2_0 = (const float*)d_in[6];
    const float* w1s  = (const float*)d_in[7];
    const float* b1s  = (const float*)d_in[8];
    const float* w2s  = (const float*)d_in[9];
    const float* b2s  = (const float*)d_in[10];
    float* out = (float*)d_out;

    float *z, *h;
    uint2* t2;
    uint4* wf;
    cudaGetSymbolAddress((void**)&z, g_z);
    cudaGetSymbolAddress((void**)&h, g_h);
    cudaGetSymbolAddress((void**)&t2, g_t2);
    cudaGetSymbolAddress((void**)&wf, g_wf);

    dim3 ggrid((NNODES + BM - 1) / BM, HID / BN);  // (391, 2)

    // ncu captures launch index 3 -> k_gemm1 (layer 0).
    k_init_copy<<<2048, 256>>>(out, (const float4*)x, (float4*)z);              // 0
    k_detect_cvt<<<960, 256>>>((const unsigned*)ei, (const unsigned*)ba,        // 1
                               w1_0, w2_0, w1s, w2s);
    k_scatter<<<4736, 256>>>(x, z, ei, 5);                                      // 2
    k_gemm1<<<ggrid, 256>>>(z, wf + W1_0_F, b1_0, t2, INC);                     // 3 <- profiled
    k_gemm2<<<ggrid, 256>>>(t2, wf + W2_0_F, b2_0, h, z, nullptr, nullptr, HID);

    for (int l = 0; l < 3; l++) {
        k_scatter<<<4736, 256>>>(h, z, ei, 6);
        k_gemm1<<<ggrid, 256>>>(z, wf + W1S_F + l * 16384, b1s + l * HID, t2, HID);
        if (l < 2) {
            k_gemm2<<<ggrid, 256>>>(t2, wf + W2S_F + l * 16384, b2s + l * HID,
                                    h, z, nullptr, nullptr, HID);
        } else {
            k_gemm2<<<ggrid, 256>>>(t2, wf + W2S_F + l * 16384, b2s + l * HID,
                                    nullptr, nullptr, out, ba, HID);
        }
    }
}